// round 7
// baseline (speedup 1.0000x reference)
#include <cuda_runtime.h>
#include <cstdint>
#include <math.h>

// ============================================================================
// AttentionModel: QKV projection + MHA + jax-threefry dropout.
//   B=2, S=2048, D=1024, H=16, HD=64
// Round 6 design (resubmit; prior run died to container infra):
// threefry mask generation moved into the projection launch (interleaved
// blocks -> alu pipe overlaps tensor pipe); attention kernel consumes
// precomputed mask bits and runs at 2 blocks/SM.
// ============================================================================

static constexpr int B_ = 2, H_ = 16, S_ = 2048, D_ = 1024, HD_ = 64;
static constexpr unsigned MASK_WORDS = (unsigned)B_ * H_ * S_ * (S_ / 32);  // 4,194,304

__device__ float g_q[B_ * S_ * D_];
__device__ float g_k[B_ * S_ * D_];
__device__ float g_v[B_ * S_ * D_];
__device__ unsigned g_drop[MASK_WORDS];  // bit i of word w = keep(idx = 32w + i)

// ---------------------------------------------------------------------------
// tf32 helpers
// ---------------------------------------------------------------------------
__device__ __forceinline__ float f2tf32f(float x) {
    uint32_t r;
    asm("cvt.rna.tf32.f32 %0, %1;" : "=r"(r) : "f"(x));
    return __uint_as_float(r);
}

__device__ __forceinline__ void mma_tf32(float c[4],
                                         uint32_t a0, uint32_t a1, uint32_t a2, uint32_t a3,
                                         uint32_t b0, uint32_t b1) {
    asm volatile(
        "mma.sync.aligned.m16n8k8.row.col.f32.tf32.tf32.f32 "
        "{%0,%1,%2,%3}, {%4,%5,%6,%7}, {%8,%9}, {%0,%1,%2,%3};"
        : "+f"(c[0]), "+f"(c[1]), "+f"(c[2]), "+f"(c[3])
        : "r"(a0), "r"(a1), "r"(a2), "r"(a3), "r"(b0), "r"(b1));
}

// ---------------------------------------------------------------------------
// Threefry-2x32 (JAX partitionable scheme) — verified exact in Round 2.
// keep(idx) <=> uniform(key, ...)[idx] < 0.9  <=>  bits < 3865470464u
// (u = (bits>>9)*2^-23 exactly; 0.9f = 7549747*2^-23; integer compare exact.)
// ---------------------------------------------------------------------------
struct KeyPair { unsigned a, b; };

__host__ __device__ constexpr unsigned rotlc(unsigned x, int r) {
    return (x << r) | (x >> (32 - r));
}

__host__ __device__ constexpr KeyPair threefry_block(unsigned k0, unsigned k1,
                                                     unsigned x0, unsigned x1) {
    unsigned k2 = k0 ^ k1 ^ 0x1BD11BDAu;
    x0 += k0; x1 += k1;
    const int RA[4] = {13, 15, 26, 6};
    const int RB[4] = {17, 29, 16, 24};
    for (int i = 0; i < 4; i++) { x0 += x1; x1 = rotlc(x1, RA[i]); x1 ^= x0; }
    x0 += k1; x1 += k2 + 1u;
    for (int i = 0; i < 4; i++) { x0 += x1; x1 = rotlc(x1, RB[i]); x1 ^= x0; }
    x0 += k2; x1 += k0 + 2u;
    for (int i = 0; i < 4; i++) { x0 += x1; x1 = rotlc(x1, RA[i]); x1 ^= x0; }
    x0 += k0; x1 += k1 + 3u;
    for (int i = 0; i < 4; i++) { x0 += x1; x1 = rotlc(x1, RB[i]); x1 ^= x0; }
    x0 += k1; x1 += k2 + 4u;
    for (int i = 0; i < 4; i++) { x0 += x1; x1 = rotlc(x1, RA[i]); x1 ^= x0; }
    x0 += k2; x1 += k0 + 5u;
    return {x0, x1};
}

__device__ __forceinline__ bool keep_bit(unsigned idx) {
    constexpr KeyPair FK = threefry_block(0u, 0u, 0u, 12345u);
    KeyPair r = threefry_block(FK.a, FK.b, 0u, idx);
    return (r.a ^ r.b) < 3865470464u;
}

// ---------------------------------------------------------------------------
// Fused projections + dropout-mask generation.
// Grid 2048 x 256thr: blocks with bx%4<3 do a 128x64 GEMM tile of matrix
// (bx%4); blocks with bx%4==3 generate 8192 mask words each (warp ballot,
// 4 independent threefry chains per lane).
// ---------------------------------------------------------------------------
__global__ void __launch_bounds__(256) proj_mask_kernel(
    const float* __restrict__ Xq, const float* __restrict__ Xk, const float* __restrict__ Xv,
    const float* __restrict__ Wq, const float* __restrict__ Wk, const float* __restrict__ Wv,
    const float* __restrict__ bq, const float* __restrict__ bk, const float* __restrict__ bv) {
    const int bx = blockIdx.x;
    const int rsel = bx & 3;
    const int g = bx >> 2;
    const int t = threadIdx.x;
    const int lane = t & 31;

    if (rsel == 3) {
        // ---- mask generation: words [g*8192, (g+1)*8192) ----
        const unsigned wbase = (unsigned)g * 8192u + (unsigned)(t >> 5) * 1024u;
        for (unsigned wi = 0; wi < 1024; wi += 4) {
            const unsigned w0 = wbase + wi;
            const bool k0 = keep_bit((w0 + 0u) * 32u + lane);
            const bool k1 = keep_bit((w0 + 1u) * 32u + lane);
            const bool k2 = keep_bit((w0 + 2u) * 32u + lane);
            const bool k3 = keep_bit((w0 + 3u) * 32u + lane);
            const unsigned b0 = __ballot_sync(0xffffffffu, k0);
            const unsigned b1 = __ballot_sync(0xffffffffu, k1);
            const unsigned b2 = __ballot_sync(0xffffffffu, k2);
            const unsigned b3 = __ballot_sync(0xffffffffu, k3);
            if (lane == 0) g_drop[w0 + 0] = b0;
            if (lane == 1) g_drop[w0 + 1] = b1;
            if (lane == 2) g_drop[w0 + 2] = b2;
            if (lane == 3) g_drop[w0 + 3] = b3;
        }
        return;
    }

    // ---- GEMM path ----
    __shared__ float Xs[128 * 36];
    __shared__ float Ws[64 * 36];

    const float* X    = (rsel == 0) ? Xq : (rsel == 1) ? Xk : Xv;
    const float* W    = (rsel == 0) ? Wq : (rsel == 1) ? Wk : Wv;
    const float* bias = (rsel == 0) ? bq : (rsel == 1) ? bk : bv;
    float*       Y    = (rsel == 0) ? g_q : (rsel == 1) ? g_k : g_v;

    const int m0 = (g & 31) << 7;
    const int n0 = (g >> 5) << 6;
    const int w = t >> 5;
    const int grp = lane >> 2, qd = lane & 3;
    const int wm = w >> 1, wn = w & 1;
    const int frow = t >> 3;
    const int fc4  = (t & 7) << 2;

    float acc[2][4][4];
    #pragma unroll
    for (int mt = 0; mt < 2; mt++)
        #pragma unroll
        for (int nt = 0; nt < 4; nt++)
            #pragma unroll
            for (int r = 0; r < 4; r++) acc[mt][nt][r] = 0.0f;

    const float* xa0 = &Xs[(wm * 32 + grp) * 36 + qd];
    const float* xa1 = &Xs[(wm * 32 + 16 + grp) * 36 + qd];
    const float* wb  = &Ws[(wn * 32 + grp) * 36 + qd];

    for (int k0 = 0; k0 < D_; k0 += 32) {
        __syncthreads();
        #pragma unroll
        for (int l = 0; l < 4; l++) {
            const int row = frow + (l << 5);
            float4 v = *reinterpret_cast<const float4*>(&X[(size_t)(m0 + row) * D_ + k0 + fc4]);
            float* d = &Xs[row * 36 + fc4];
            d[0] = f2tf32f(v.x); d[1] = f2tf32f(v.y); d[2] = f2tf32f(v.z); d[3] = f2tf32f(v.w);
        }
        #pragma unroll
        for (int l = 0; l < 2; l++) {
            const int row = frow + (l << 5);
            float4 v = *reinterpret_cast<const float4*>(&W[(size_t)(n0 + row) * D_ + k0 + fc4]);
            float* d = &Ws[row * 36 + fc4];
            d[0] = f2tf32f(v.x); d[1] = f2tf32f(v.y); d[2] = f2tf32f(v.z); d[3] = f2tf32f(v.w);
        }
        __syncthreads();

        #pragma unroll
        for (int k8 = 0; k8 < 4; k8++) {
            const int kk = k8 << 3;
            uint32_t a[2][4];
            #pragma unroll
            for (int mt = 0; mt < 2; mt++) {
                const float* base = mt ? xa1 : xa0;
                a[mt][0] = __float_as_uint(base[kk]);
                a[mt][1] = __float_as_uint(base[8 * 36 + kk]);
                a[mt][2] = __float_as_uint(base[kk + 4]);
                a[mt][3] = __float_as_uint(base[8 * 36 + kk + 4]);
            }
            #pragma unroll
            for (int nt = 0; nt < 4; nt++) {
                uint32_t b0 = __float_as_uint(wb[nt * 8 * 36 + kk]);
                uint32_t b1 = __float_as_uint(wb[nt * 8 * 36 + kk + 4]);
                mma_tf32(acc[0][nt], a[0][0], a[0][1], a[0][2], a[0][3], b0, b1);
                mma_tf32(acc[1][nt], a[1][0], a[1][1], a[1][2], a[1][3], b0, b1);
            }
        }
    }

    #pragma unroll
    for (int mt = 0; mt < 2; mt++) {
        const int r0 = m0 + wm * 32 + mt * 16 + grp;
        #pragma unroll
        for (int nt = 0; nt < 4; nt++) {
            const int c = n0 + wn * 32 + nt * 8 + (qd << 1);
            const float b0 = bias[c], b1 = bias[c + 1];
            float2 v0 = make_float2(acc[mt][nt][0] + b0, acc[mt][nt][1] + b1);
            float2 v1 = make_float2(acc[mt][nt][2] + b0, acc[mt][nt][3] + b1);
            *reinterpret_cast<float2*>(&Y[(size_t)r0 * D_ + c]) = v0;
            *reinterpret_cast<float2*>(&Y[(size_t)(r0 + 8) * D_ + c]) = v1;
        }
    }
}

// ---------------------------------------------------------------------------
// Flash attention (tf32 mma): grid (S/128, B*H), 256 thr (8 warps), 2 blk/SM.
// smem: Qs[128][72] swz | Ks[64][72] swz | Vs[64][72] plain | Ps[128][72] swz
// ---------------------------------------------------------------------------
static constexpr int ATTN_SMEM_FLOATS = 128 * 72 + 64 * 72 + 64 * 72 + 128 * 72 + 64;
static constexpr int ATTN_SMEM_BYTES  = ATTN_SMEM_FLOATS * 4;

__global__ void __launch_bounds__(256, 2) attn_mma_kernel(const int* __restrict__ mask,
                                                          const float* __restrict__ inv_scale_p,
                                                          float* __restrict__ out) {
    extern __shared__ float sm[];
    float* Qs = sm;                       // 128 x 72, xor-swizzled quads
    float* Ks = Qs + 128 * 72;            // 64 x 72, xor-swizzled
    float* Vs = Ks + 64 * 72;             // 64 x 72, plain
    float* Ps = Vs + 64 * 72;             // 128 x 72, xor-swizzled
    int*   Ms = (int*)(Ps + 128 * 72);    // 64

    const int q0 = blockIdx.x << 7;
    const int bh = blockIdx.y;
    const int b  = bh >> 4;
    const int hcol = (bh & 15) << 6;
    const int t = threadIdx.x;
    const int lane = t & 31, w = t >> 5;
    const int grp = lane >> 2, qd = lane & 3;
    const int R0 = (w << 4) + grp;
    const int sw0 = R0 & 15, sw1 = (R0 + 8) & 15;
    const float scale = 1.0f / inv_scale_p[0];

    float* Q0 = &Qs[R0 * 72];
    float* Q1 = &Qs[(R0 + 8) * 72];
    float* P0 = &Ps[R0 * 72];
    float* P1 = &Ps[(R0 + 8) * 72];

    // ---- load Q tile (swizzled, tf32) ----
    {
        const int cq = t & 15;
        #pragma unroll
        for (int l = 0; l < 8; l++) {
            const int row = (t >> 4) + (l << 4);
            float4 v = *reinterpret_cast<const float4*>(
                &g_q[(size_t)(b * S_ + q0 + row) * D_ + hcol + (cq << 2)]);
            float* d = &Qs[row * 72 + ((cq ^ (row & 15)) << 2)];
            d[0] = f2tf32f(v.x); d[1] = f2tf32f(v.y); d[2] = f2tf32f(v.z); d[3] = f2tf32f(v.w);
        }
    }

    float oacc[8][4];
    #pragma unroll
    for (int nt = 0; nt < 8; nt++)
        #pragma unroll
        for (int r = 0; r < 4; r++) oacc[nt][r] = 0.0f;
    float mrow0 = -INFINITY, mrow1 = -INFINITY;
    float lrow0 = 0.0f, lrow1 = 0.0f;

    const unsigned rb0 = ((unsigned)bh * S_ + (unsigned)(q0 + R0)) * (unsigned)S_;
    const unsigned rb1 = rb0 + 8u * S_;

    for (int kt = 0; kt < S_ / 64; kt++) {
        const int kbase = kt << 6;
        __syncthreads();
        // ---- K/V tile fill ----
        {
            const int cq = t & 15;
            #pragma unroll
            for (int l = 0; l < 4; l++) {
                const int row = (t >> 4) + (l << 4);
                const size_t gof = (size_t)(b * S_ + kbase + row) * D_ + hcol + (cq << 2);
                float4 kv = *reinterpret_cast<const float4*>(&g_k[gof]);
                float* dk = &Ks[row * 72 + ((cq ^ (row & 15)) << 2)];
                dk[0] = f2tf32f(kv.x); dk[1] = f2tf32f(kv.y);
                dk[2] = f2tf32f(kv.z); dk[3] = f2tf32f(kv.w);
                float4 vv = *reinterpret_cast<const float4*>(&g_v[gof]);
                float* dv = &Vs[row * 72 + (cq << 2)];
                dv[0] = f2tf32f(vv.x); dv[1] = f2tf32f(vv.y);
                dv[2] = f2tf32f(vv.z); dv[3] = f2tf32f(vv.w);
            }
            if (t < 64) Ms[t] = mask[b * S_ + kbase + t];
        }
        // dropout mask words for this tile (row-aligned; 8B aligned)
        const uint2 dwa = *reinterpret_cast<const uint2*>(&g_drop[(rb0 + (unsigned)kbase) >> 5]);
        const uint2 dwb = *reinterpret_cast<const uint2*>(&g_drop[(rb1 + (unsigned)kbase) >> 5]);
        __syncthreads();

        // ---- S = Q K^T ----
        float sacc[8][4];
        #pragma unroll
        for (int nt = 0; nt < 8; nt++)
            #pragma unroll
            for (int r = 0; r < 4; r++) sacc[nt][r] = 0.0f;

        #pragma unroll
        for (int k8 = 0; k8 < 8; k8++) {
            const int cqa = 2 * k8;
            uint32_t a0 = __float_as_uint(Q0[((cqa ^ sw0) << 2) + qd]);
            uint32_t a1 = __float_as_uint(Q1[((cqa ^ sw1) << 2) + qd]);
            uint32_t a2 = __float_as_uint(Q0[(((cqa + 1) ^ sw0) << 2) + qd]);
            uint32_t a3 = __float_as_uint(Q1[(((cqa + 1) ^ sw1) << 2) + qd]);
            #pragma unroll
            for (int nt = 0; nt < 8; nt++) {
                const int key = (nt << 3) + grp;
                const int ksw = key & 15;
                const float* kr = &Ks[key * 72];
                uint32_t b0 = __float_as_uint(kr[((cqa ^ ksw) << 2) + qd]);
                uint32_t b1 = __float_as_uint(kr[(((cqa + 1) ^ ksw) << 2) + qd]);
                mma_tf32(sacc[nt], a0, a1, a2, a3, b0, b1);
            }
        }

        // ---- mask + scale ----
        #pragma unroll
        for (int nt = 0; nt < 8; nt++) {
            const int col = (nt << 3) + (qd << 1);
            const int mu0 = Ms[col], mu1 = Ms[col + 1];
            sacc[nt][0] = mu0 ? sacc[nt][0] * scale : -INFINITY;
            sacc[nt][1] = mu1 ? sacc[nt][1] * scale : -INFINITY;
            sacc[nt][2] = mu0 ? sacc[nt][2] * scale : -INFINITY;
            sacc[nt][3] = mu1 ? sacc[nt][3] * scale : -INFINITY;
        }

        // ---- row max (quad shuffle) ----
        float mx0 = -INFINITY, mx1 = -INFINITY;
        #pragma unroll
        for (int nt = 0; nt < 8; nt++) {
            mx0 = fmaxf(mx0, fmaxf(sacc[nt][0], sacc[nt][1]));
            mx1 = fmaxf(mx1, fmaxf(sacc[nt][2], sacc[nt][3]));
        }
        #pragma unroll
        for (int o = 1; o < 4; o <<= 1) {
            mx0 = fmaxf(mx0, __shfl_xor_sync(0xffffffffu, mx0, o));
            mx1 = fmaxf(mx1, __shfl_xor_sync(0xffffffffu, mx1, o));
        }
        const float mn0 = fmaxf(mrow0, mx0);
        const float mn1 = fmaxf(mrow1, mx1);
        const float me0 = (mn0 == -INFINITY) ? 0.0f : mn0;
        const float me1 = (mn1 == -INFINITY) ? 0.0f : mn1;
        const float cf0 = (mrow0 == -INFINITY) ? ((mn0 == -INFINITY) ? 1.0f : 0.0f)
                                               : __expf(mrow0 - me0);
        const float cf1 = (mrow1 == -INFINITY) ? ((mn1 == -INFINITY) ? 1.0f : 0.0f)
                                               : __expf(mrow1 - me1);

        // ---- exp, dropout (bit lookup), P store ----
        float rs0 = 0.0f, rs1 = 0.0f;
        #pragma unroll
        for (int nt = 0; nt < 8; nt++) {
            const int col = (nt << 3) + (qd << 1);
            const unsigned wa = (nt < 4) ? dwa.x : dwa.y;
            const unsigned wb2 = (nt < 4) ? dwb.x : dwb.y;
            const int sh = col & 31;
            const float p00 = __expf(sacc[nt][0] - me0);
            const float p01 = __expf(sacc[nt][1] - me0);
            const float p10 = __expf(sacc[nt][2] - me1);
            const float p11 = __expf(sacc[nt][3] - me1);
            rs0 += p00 + p01;
            rs1 += p10 + p11;
            const float d00 = ((wa  >> sh) & 1u)       ? p00 * (1.0f / 0.9f) : 0.0f;
            const float d01 = ((wa  >> (sh + 1)) & 1u) ? p01 * (1.0f / 0.9f) : 0.0f;
            const float d10 = ((wb2 >> sh) & 1u)       ? p10 * (1.0f / 0.9f) : 0.0f;
            const float d11 = ((wb2 >> (sh + 1)) & 1u) ? p11 * (1.0f / 0.9f) : 0.0f;
            const int pcq = (nt << 1) + (qd >> 1);
            const int lo  = (qd & 1) << 1;
            *reinterpret_cast<float2*>(&P0[((pcq ^ sw0) << 2) + lo]) =
                make_float2(f2tf32f(d00), f2tf32f(d01));
            *reinterpret_cast<float2*>(&P1[((pcq ^ sw1) << 2) + lo]) =
                make_float2(f2tf32f(d10), f2tf32f(d11));
        }
        #pragma unroll
        for (int o = 1; o < 4; o <<= 1) {
            rs0 += __shfl_xor_sync(0xffffffffu, rs0, o);
            rs1 += __shfl_xor_sync(0xffffffffu, rs1, o);
        }
        lrow0 = lrow0 * cf0 + rs0;
        lrow1 = lrow1 * cf1 + rs1;
        mrow0 = mn0;
        mrow1 = mn1;
        #pragma unroll
        for (int nt = 0; nt < 8; nt++) {
            oacc[nt][0] *= cf0; oacc[nt][1] *= cf0;
            oacc[nt][2] *= cf1; oacc[nt][3] *= cf1;
        }
        __syncwarp();

        // ---- O += P V ----
        #pragma unroll
        for (int k8 = 0; k8 < 8; k8++) {
            const int cqa = 2 * k8;
            uint32_t a0 = __float_as_uint(P0[((cqa ^ sw0) << 2) + qd]);
            uint32_t a1 = __float_as_uint(P1[((cqa ^ sw1) << 2) + qd]);
            uint32_t a2 = __float_as_uint(P0[(((cqa + 1) ^ sw0) << 2) + qd]);
            uint32_t a3 = __float_as_uint(P1[(((cqa + 1) ^ sw1) << 2) + qd]);
            const float* v0 = &Vs[((k8 << 3) + qd) * 72 + grp];
            #pragma unroll
            for (int nt = 0; nt < 8; nt++) {
                uint32_t b0 = __float_as_uint(v0[nt << 3]);
                uint32_t b1 = __float_as_uint(v0[4 * 72 + (nt << 3)]);
                mma_tf32(oacc[nt], a0, a1, a2, a3, b0, b1);
            }
        }
    }

    // ---- epilogue ----
    const float il0 = 1.0f / lrow0;
    const float il1 = 1.0f / lrow1;
    const size_t g0 = ((size_t)bh * S_ + q0 + R0) * HD_;
    const size_t g1 = ((size_t)bh * S_ + q0 + R0 + 8) * HD_;
    #pragma unroll
    for (int nt = 0; nt < 8; nt++) {
        const int col = (nt << 3) + (qd << 1);
        *reinterpret_cast<float2*>(&out[g0 + col]) =
            make_float2(oacc[nt][0] * il0, oacc[nt][1] * il0);
        *reinterpret_cast<float2*>(&out[g1 + col]) =
            make_float2(oacc[nt][2] * il1, oacc[nt][3] * il1);
    }
}

// ---------------------------------------------------------------------------
extern "C" void kernel_launch(void* const* d_in, const int* in_sizes, int n_in,
                              void* d_out, int out_size) {
    (void)in_sizes; (void)n_in; (void)out_size;
    const float* query = (const float*)d_in[0];
    const float* key   = (const float*)d_in[1];
    const float* value = (const float*)d_in[2];
    const int*   mask  = (const int*)d_in[3];
    const float* invsc = (const float*)d_in[4];
    const float* Wq    = (const float*)d_in[5];
    const float* bq    = (const float*)d_in[6];
    const float* Wk    = (const float*)d_in[7];
    const float* bk    = (const float*)d_in[8];
    const float* Wv    = (const float*)d_in[9];
    const float* bv    = (const float*)d_in[10];
    float*       out   = (float*)d_out;

    proj_mask_kernel<<<2048, 256>>>(query, key, value, Wq, Wk, Wv, bq, bk, bv);

    cudaFuncSetAttribute(attn_mma_kernel, cudaFuncAttributeMaxDynamicSharedMemorySize,
                         ATTN_SMEM_BYTES);
    dim3 ag(S_ / 128, B_ * H_);
    attn_mma_kernel<<<ag, 256, ATTN_SMEM_BYTES>>>(mask, invsc, out);
}